// round 1
// baseline (speedup 1.0000x reference)
#include <cuda_runtime.h>
#include <math.h>

#define NN   1024            // nodes
#define NE   (32 * NN)       // edges
#define CI   8               // in channels
#define NM1  1023
#define PP   (NN * NM1)      // pairs

// ---- scratch (device globals; allocation-free) ----
__device__ float g_deg_out[NN];
__device__ float g_deg_in[NN];
__device__ float g_pfx[NN * CI];
__device__ float g_pbx[NN * CI];
// A at [n*16+0..4], B at [n*16+8..12] (padded row = 64B cache line)
__device__ float g_AB[NN * 16];

// ---------------------------------------------------------------- zero
__global__ void k_zero() {
    int i = blockIdx.x * blockDim.x + threadIdx.x;
    if (i < NN) { g_deg_out[i] = 0.f; g_deg_in[i] = 0.f; }
    if (i < NN * CI) { g_pfx[i] = 0.f; g_pbx[i] = 0.f; }
}

// ---------------------------------------------------------------- degrees
__global__ void k_deg(const int* __restrict__ ei, const float* __restrict__ w) {
    int e = blockIdx.x * blockDim.x + threadIdx.x;
    if (e >= NE) return;
    int r = ei[e];
    int c = ei[NE + e];
    float we = w[e];
    atomicAdd(&g_deg_out[r], we);
    atomicAdd(&g_deg_in[c], we);
}

// ---------------------------------------------------------------- edge aggregation
// pf(x)[col] += x[row]/deg_out[row];  pb(x)[row] += x[col]/deg_in[row]
__global__ void k_agg(const int* __restrict__ ei, const float* __restrict__ x) {
    int idx = blockIdx.x * blockDim.x + threadIdx.x;   // edge*8 + ch
    if (idx >= NE * CI) return;
    int e  = idx >> 3;
    int ch = idx & 7;
    int r = ei[e];
    int c = ei[NE + e];
    float inv_do = 1.f / g_deg_out[r];
    float inv_di = 1.f / g_deg_in[r];   // reference indexes deg_in by ROW (quirk kept)
    atomicAdd(&g_pfx[c * CI + ch], inv_do * x[r * CI + ch]);
    atomicAdd(&g_pbx[r * CI + ch], inv_di * x[c * CI + ch]);
}

// ---------------------------------------------------------------- per-node GRU + A/B
// One warp per node; lane = output channel c (0..31).
// z = bz[c] + x·(Wz[0,0]+Wz[1,0]) + pfx·Wz[0,1] + pbx·Wz[1,1]   (rows 0:8 only)
// H = (1 - sigmoid(z)) * tanh(h);  o = relu(H)
// A[n][m] = sum_c o_c*w1[c][m] + sum_k x_k*w1[32+k][m]
// B[n][m] = sum_c o_c*w1[40+c][m] + sum_k x_k*w1[72+k][m]
__global__ void k_node(const float* __restrict__ x,
                       const float* __restrict__ Wz, const float* __restrict__ bz,
                       const float* __restrict__ Wh, const float* __restrict__ bh,
                       const float* __restrict__ w1) {
    int gwarp = (blockIdx.x * blockDim.x + threadIdx.x) >> 5;
    int lane  = threadIdx.x & 31;
    if (gwarp >= NN) return;
    const int n = gwarp, c = lane;

    float xv[8], pf[8], pb[8];
#pragma unroll
    for (int k = 0; k < 8; k++) {
        xv[k] = x[n * 8 + k];
        pf[k] = g_pfx[n * 8 + k];
        pb[k] = g_pbx[n * 8 + k];
    }

    // W layout [2][2][40][32] row-major: block b (= d*2+kk) at offset b*1280
    float z = bz[c];
    float h = bh[c];
#pragma unroll
    for (int k = 0; k < 8; k++) {
        int o0 = 0 * 1280 + k * 32 + c;   // W[0,0]
        int o1 = 1 * 1280 + k * 32 + c;   // W[0,1]
        int o2 = 2 * 1280 + k * 32 + c;   // W[1,0]
        int o3 = 3 * 1280 + k * 32 + c;   // W[1,1]
        z += xv[k] * (Wz[o0] + Wz[o2]) + pf[k] * Wz[o1] + pb[k] * Wz[o3];
        h += xv[k] * (Wh[o0] + Wh[o2]) + pf[k] * Wh[o1] + pb[k] * Wh[o3];
    }
    float sig = 1.f / (1.f + expf(-z));
    float Hn  = (1.f - sig) * tanhf(h);
    float o   = fmaxf(Hn, 0.f);

    float a[5], b5[5];
#pragma unroll
    for (int m = 0; m < 5; m++) {
        float ta = o * w1[c * 5 + m];
        float tb = o * w1[(40 + c) * 5 + m];
        if (c < 8) {
            ta += xv[c] * w1[(32 + c) * 5 + m];
            tb += xv[c] * w1[(72 + c) * 5 + m];
        }
        a[m] = ta; b5[m] = tb;
    }
#pragma unroll
    for (int m = 0; m < 5; m++) {
#pragma unroll
        for (int s = 16; s > 0; s >>= 1) {
            a[m]  += __shfl_xor_sync(0xffffffffu, a[m],  s);
            b5[m] += __shfl_xor_sync(0xffffffffu, b5[m], s);
        }
    }
    if (lane == 0) {
#pragma unroll
        for (int m = 0; m < 5; m++) {
            g_AB[n * 16 + m]     = a[m];
            g_AB[n * 16 + 8 + m] = b5[m];
        }
    }
}

// ---------------------------------------------------------------- pair MLP (the big one)
// 4 pairs per thread, float4 streaming loads/stores; small weights staged in smem.
__global__ void __launch_bounds__(256)
k_pairs(const float* __restrict__ dist, const float* __restrict__ lags,
        const float* __restrict__ lz_,  const float* __restrict__ a2d,
        const float* __restrict__ a2o,  const float* __restrict__ d2a,
        const float* __restrict__ o2a,  const float* __restrict__ vr,
        const float* __restrict__ w1,   const float* __restrict__ b1,
        const float* __restrict__ w2,   const float* __restrict__ b2,
        const float* __restrict__ w3,   const float* __restrict__ b3,
        const float* __restrict__ w4,   const float* __restrict__ b4,
        float* __restrict__ out) {
    // staged weights: w1 rows 80..88 (45), b1(5), w2(15), b2(3), w3(3), w4(2), b3, b4
    __shared__ float sw1[45], sb1[5], sw2[15], sb2[3], sw3[3], sw4[2], sb34[2];
    int t = threadIdx.x;
    if (t < 45) sw1[t] = w1[400 + t];          // w1[(80+f)*5+m] flat
    else if (t < 50) sb1[t - 45] = b1[t - 45];
    else if (t < 65) sw2[t - 50] = w2[t - 50];
    else if (t < 68) sb2[t - 65] = b2[t - 65];
    else if (t < 71) sw3[t - 68] = w3[t - 68];
    else if (t < 73) sw4[t - 71] = w4[t - 71];
    else if (t == 73) sb34[0] = b3[0];
    else if (t == 74) sb34[1] = b4[0];
    __syncthreads();

    int tid = blockIdx.x * blockDim.x + threadIdx.x;
    int p0  = tid * 4;
    if (p0 >= PP) return;

    float4 v_d  = *(const float4*)(dist + p0);
    float4 v_lg = *(const float4*)(lags + p0);
    float4 v_z0 = *(const float4*)(lz_  + p0);
    float4 v_td = *(const float4*)(a2d  + p0);
    float4 v_to = *(const float4*)(a2o  + p0);
    float4 v_da = *(const float4*)(d2a  + p0);
    float4 v_oa = *(const float4*)(o2a  + p0);
    float4 v_vv = *(const float4*)(vr   + p0);
    float dA[4]  = {v_d.x,  v_d.y,  v_d.z,  v_d.w};
    float lgA[4] = {v_lg.x, v_lg.y, v_lg.z, v_lg.w};
    float z0A[4] = {v_z0.x, v_z0.y, v_z0.z, v_z0.w};
    float tdA[4] = {v_td.x, v_td.y, v_td.z, v_td.w};
    float toA[4] = {v_to.x, v_to.y, v_to.z, v_to.w};
    float daA[4] = {v_da.x, v_da.y, v_da.z, v_da.w};
    float oaA[4] = {v_oa.x, v_oa.y, v_oa.z, v_oa.w};
    float vvA[4] = {v_vv.x, v_vv.y, v_vv.z, v_vv.w};

    unsigned i = (unsigned)p0 / 1023u;
    unsigned k = (unsigned)p0 - i * 1023u;

    float y[4];
#pragma unroll
    for (int r = 0; r < 4; r++) {
        unsigned j = (k < i) ? k : (k + 1u);
        const float* Ai = g_AB + i * 16u;
        const float* Bj = g_AB + j * 16u + 8u;
        float d = dA[r], lg = lgA[r], z0 = z0A[r];
        float td = tdA[r], to = toA[r], da = daA[r], oa = oaA[r], vv = vvA[r];

        float h1[5];
#pragma unroll
        for (int m = 0; m < 5; m++) {
            float v = Ai[m] + Bj[m] + sb1[m];
            v += d  * (sw1[0 * 5 + m] + d * sw1[1 * 5 + m]);   // dist, dist^2
            v += lg * sw1[2 * 5 + m];
            v += z0 * sw1[3 * 5 + m];
            v += td * sw1[4 * 5 + m];
            v += to * sw1[5 * 5 + m];
            v += da * sw1[6 * 5 + m];
            v += oa * sw1[7 * 5 + m];
            v += vv * sw1[8 * 5 + m];
            h1[m] = fmaxf(v, 0.f);
        }
        float h2[3];
#pragma unroll
        for (int q = 0; q < 3; q++) {
            float v = sb2[q];
#pragma unroll
            for (int m = 0; m < 5; m++) v += h1[m] * sw2[m * 3 + q];
            h2[q] = fmaxf(v, 0.f);
        }
        float h3 = sb34[0] + h2[0] * sw3[0] + h2[1] * sw3[1] + h2[2] * sw3[2];
        y[r] = h3 * sw4[0] + h3 * z0 * sw4[1] + sb34[1];

        k++;
        if (k == 1023u) { k = 0u; i++; }
    }
    *(float4*)(out + p0) = make_float4(y[0], y[1], y[2], y[3]);
}

// ---------------------------------------------------------------- launch
extern "C" void kernel_launch(void* const* d_in, const int* in_sizes, int n_in,
                              void* d_out, int out_size) {
    const float* x    = (const float*)d_in[0];
    const int*   ei   = (const int*)  d_in[1];
    const float* ew   = (const float*)d_in[2];
    const float* dist = (const float*)d_in[3];
    const float* lags = (const float*)d_in[4];
    const float* lz   = (const float*)d_in[5];
    const float* a2d  = (const float*)d_in[6];
    const float* a2o  = (const float*)d_in[7];
    const float* d2a  = (const float*)d_in[8];
    const float* o2a  = (const float*)d_in[9];
    const float* vr   = (const float*)d_in[10];
    const float* Wz   = (const float*)d_in[11];
    const float* bz   = (const float*)d_in[12];
    // d_in[13], d_in[14] = Wr, br — mathematically dead (H0 == 0)
    const float* Wh   = (const float*)d_in[15];
    const float* bh   = (const float*)d_in[16];
    const float* w1   = (const float*)d_in[17];
    const float* b1   = (const float*)d_in[18];
    const float* w2   = (const float*)d_in[19];
    const float* b2   = (const float*)d_in[20];
    const float* w3   = (const float*)d_in[21];
    const float* b3   = (const float*)d_in[22];
    const float* w4   = (const float*)d_in[23];
    const float* b4   = (const float*)d_in[24];
    float* out = (float*)d_out;

    k_zero<<<(NN * CI + 255) / 256, 256>>>();
    k_deg<<<(NE + 255) / 256, 256>>>(ei, ew);
    k_agg<<<(NE * CI + 255) / 256, 256>>>(ei, x);
    k_node<<<NN / 8, 256>>>(x, Wz, bz, Wh, bh, w1);   // 8 warps/block, warp per node
    k_pairs<<<PP / (256 * 4), 256>>>(dist, lags, lz, a2d, a2o, d2a, o2a, vr,
                                     w1, b1, w2, b2, w3, b3, w4, b4, out);
}

// round 2
// speedup vs baseline: 1.2903x; 1.2903x over previous
#include <cuda_runtime.h>
#include <math.h>

#define NN   1024            // nodes
#define NE   (32 * NN)       // edges
#define CI   8               // in channels
#define NM1  1023
#define PP   (NN * NM1)      // pairs

// ---- scratch (device globals; allocation-free) ----
__device__ float g_deg_out[NN];
__device__ float g_deg_in[NN];
__device__ float g_pfx[NN * CI];
__device__ float g_pbx[NN * CI];
// A at [n*16+0..4], B at [n*16+8..12] (padded row = 64B cache line)
__device__ float g_AB[NN * 16];

// vectorized global float4 reduction (sm_90+)
__device__ __forceinline__ void red4(float* p, float a, float b, float c, float d) {
    asm volatile("red.global.add.v4.f32 [%0], {%1,%2,%3,%4};"
                 :: "l"(p), "f"(a), "f"(b), "f"(c), "f"(d) : "memory");
}

// ---------------------------------------------------------------- zero
__global__ void k_zero() {
    int i = blockIdx.x * blockDim.x + threadIdx.x;
    if (i < NN) { g_deg_out[i] = 0.f; g_deg_in[i] = 0.f; }
    if (i < NN * CI) { g_pfx[i] = 0.f; g_pbx[i] = 0.f; }
}

// ---------------------------------------------------------------- degrees
__global__ void k_deg(const int* __restrict__ ei, const float* __restrict__ w) {
    int e = blockIdx.x * blockDim.x + threadIdx.x;
    if (e >= NE) return;
    int r = ei[e];
    int c = ei[NE + e];
    float we = w[e];
    atomicAdd(&g_deg_out[r], we);
    atomicAdd(&g_deg_in[c], we);
}

// ---------------------------------------------------------------- edge aggregation
// thread per EDGE: pf(x)[col] += x[row]/deg_out[row]; pb(x)[row] += x[col]/deg_in[row]
// (reference indexes deg_in by ROW — quirk kept)
__global__ void k_agg(const int* __restrict__ ei, const float* __restrict__ x) {
    int e = blockIdx.x * blockDim.x + threadIdx.x;
    if (e >= NE) return;
    int r = ei[e];
    int c = ei[NE + e];
    float inv_do = __fdividef(1.f, g_deg_out[r]);
    float inv_di = __fdividef(1.f, g_deg_in[r]);
    const float4* xr = (const float4*)(x + r * 8);
    const float4* xc = (const float4*)(x + c * 8);
    float4 a0 = xr[0], a1 = xr[1];
    float4 b0 = xc[0], b1 = xc[1];
    red4(&g_pfx[c * 8],     inv_do * a0.x, inv_do * a0.y, inv_do * a0.z, inv_do * a0.w);
    red4(&g_pfx[c * 8 + 4], inv_do * a1.x, inv_do * a1.y, inv_do * a1.z, inv_do * a1.w);
    red4(&g_pbx[r * 8],     inv_di * b0.x, inv_di * b0.y, inv_di * b0.z, inv_di * b0.w);
    red4(&g_pbx[r * 8 + 4], inv_di * b1.x, inv_di * b1.y, inv_di * b1.z, inv_di * b1.w);
}

// ---------------------------------------------------------------- per-node GRU + A/B
// Phase 1: thread = (node, out-channel). 8 nodes / 256-thread block.
//   z = bz[c] + x·(Wz[0,0]+Wz[1,0]) + pfx·Wz[0,1] + pbx·Wz[1,1]   (x-rows 0:8 only; H0==0)
//   o = relu((1 - sigmoid(z)) * tanh(h))  -> smem
// Phase 2: 80 threads: (local node, half, m): 40-long dot from smem + x for A/B.
__global__ void k_node(const float* __restrict__ x,
                       const float* __restrict__ Wz, const float* __restrict__ bz,
                       const float* __restrict__ Wh, const float* __restrict__ bh,
                       const float* __restrict__ w1) {
    __shared__ float so[8][33];
    int t = threadIdx.x;
    int wid = t >> 5, lane = t & 31;
    int n = blockIdx.x * 8 + wid;
    const int c = lane;

    // phase 1 ------------------------------------------------------
    float z = bz[c];
    float h = bh[c];
#pragma unroll
    for (int k = 0; k < 8; k++) {
        float xv = __ldg(x + n * 8 + k);
        float pf = g_pfx[n * 8 + k];
        float pb = g_pbx[n * 8 + k];
        int o0 = 0 * 1280 + k * 32 + c;   // W[0,0]
        int o1 = 1 * 1280 + k * 32 + c;   // W[0,1]
        int o2 = 2 * 1280 + k * 32 + c;   // W[1,0]
        int o3 = 3 * 1280 + k * 32 + c;   // W[1,1]
        z += xv * (__ldg(Wz + o0) + __ldg(Wz + o2)) + pf * __ldg(Wz + o1) + pb * __ldg(Wz + o3);
        h += xv * (__ldg(Wh + o0) + __ldg(Wh + o2)) + pf * __ldg(Wh + o1) + pb * __ldg(Wh + o3);
    }
    float sig = 1.f / (1.f + __expf(-z));
    float Hn  = (1.f - sig) * tanhf(h);
    so[wid][lane] = fmaxf(Hn, 0.f);
    __syncthreads();

    // phase 2 ------------------------------------------------------
    if (t < 80) {
        int ln   = t / 10;
        int q    = t - ln * 10;
        int half = q / 5;          // 0 -> A (out[ii] slot), 1 -> B (out[jj] slot)
        int m    = q - half * 5;
        int n2   = blockIdx.x * 8 + ln;
        float acc = 0.f;
#pragma unroll
        for (int cc = 0; cc < 32; cc++)
            acc += so[ln][cc] * __ldg(w1 + (half * 40 + cc) * 5 + m);
#pragma unroll
        for (int k = 0; k < 8; k++)
            acc += __ldg(x + n2 * 8 + k) * __ldg(w1 + (half * 40 + 32 + k) * 5 + m);
        g_AB[n2 * 16 + half * 8 + m] = acc;
    }
}

// ---------------------------------------------------------------- pair MLP (the big one)
// 4 pairs per thread, float4 streaming loads/stores; small weights staged in smem.
__global__ void __launch_bounds__(256)
k_pairs(const float* __restrict__ dist, const float* __restrict__ lags,
        const float* __restrict__ lz_,  const float* __restrict__ a2d,
        const float* __restrict__ a2o,  const float* __restrict__ d2a,
        const float* __restrict__ o2a,  const float* __restrict__ vr,
        const float* __restrict__ w1,   const float* __restrict__ b1,
        const float* __restrict__ w2,   const float* __restrict__ b2,
        const float* __restrict__ w3,   const float* __restrict__ b3,
        const float* __restrict__ w4,   const float* __restrict__ b4,
        float* __restrict__ out) {
    __shared__ float sw1[45], sb1[5], sw2[15], sb2[3], sw3[3], sw4[2], sb34[2];
    int t = threadIdx.x;
    if (t < 45) sw1[t] = w1[400 + t];          // w1 rows 80..88 flat
    else if (t < 50) sb1[t - 45] = b1[t - 45];
    else if (t < 65) sw2[t - 50] = w2[t - 50];
    else if (t < 68) sb2[t - 65] = b2[t - 65];
    else if (t < 71) sw3[t - 68] = w3[t - 68];
    else if (t < 73) sw4[t - 71] = w4[t - 71];
    else if (t == 73) sb34[0] = b3[0];
    else if (t == 74) sb34[1] = b4[0];
    __syncthreads();

    int tid = blockIdx.x * blockDim.x + threadIdx.x;
    int p0  = tid * 4;
    if (p0 >= PP) return;

    float4 v_d  = *(const float4*)(dist + p0);
    float4 v_lg = *(const float4*)(lags + p0);
    float4 v_z0 = *(const float4*)(lz_  + p0);
    float4 v_td = *(const float4*)(a2d  + p0);
    float4 v_to = *(const float4*)(a2o  + p0);
    float4 v_da = *(const float4*)(d2a  + p0);
    float4 v_oa = *(const float4*)(o2a  + p0);
    float4 v_vv = *(const float4*)(vr   + p0);
    float dA[4]  = {v_d.x,  v_d.y,  v_d.z,  v_d.w};
    float lgA[4] = {v_lg.x, v_lg.y, v_lg.z, v_lg.w};
    float z0A[4] = {v_z0.x, v_z0.y, v_z0.z, v_z0.w};
    float tdA[4] = {v_td.x, v_td.y, v_td.z, v_td.w};
    float toA[4] = {v_to.x, v_to.y, v_to.z, v_to.w};
    float daA[4] = {v_da.x, v_da.y, v_da.z, v_da.w};
    float oaA[4] = {v_oa.x, v_oa.y, v_oa.z, v_oa.w};
    float vvA[4] = {v_vv.x, v_vv.y, v_vv.z, v_vv.w};

    unsigned i = (unsigned)p0 / 1023u;
    unsigned k = (unsigned)p0 - i * 1023u;

    // A for current i (reloaded only if i advances mid-thread)
    float4 Ai4 = *(const float4*)(g_AB + i * 16u);
    float  Ai4e = g_AB[i * 16u + 4u];

    float y[4];
#pragma unroll
    for (int r = 0; r < 4; r++) {
        unsigned j = (k < i) ? k : (k + 1u);
        float4 Bj4  = *(const float4*)(g_AB + j * 16u + 8u);
        float  Bj4e = g_AB[j * 16u + 12u];
        float AiB[5] = {Ai4.x + Bj4.x, Ai4.y + Bj4.y, Ai4.z + Bj4.z,
                        Ai4.w + Bj4.w, Ai4e + Bj4e};
        float d = dA[r], lg = lgA[r], z0 = z0A[r];
        float td = tdA[r], to = toA[r], da = daA[r], oa = oaA[r], vv = vvA[r];

        float h1[5];
#pragma unroll
        for (int m = 0; m < 5; m++) {
            float v = AiB[m] + sb1[m];
            v += d  * (sw1[0 * 5 + m] + d * sw1[1 * 5 + m]);   // dist, dist^2
            v += lg * sw1[2 * 5 + m];
            v += z0 * sw1[3 * 5 + m];
            v += td * sw1[4 * 5 + m];
            v += to * sw1[5 * 5 + m];
            v += da * sw1[6 * 5 + m];
            v += oa * sw1[7 * 5 + m];
            v += vv * sw1[8 * 5 + m];
            h1[m] = fmaxf(v, 0.f);
        }
        float h2[3];
#pragma unroll
        for (int q = 0; q < 3; q++) {
            float v = sb2[q];
#pragma unroll
            for (int m = 0; m < 5; m++) v += h1[m] * sw2[m * 3 + q];
            h2[q] = fmaxf(v, 0.f);
        }
        float h3 = sb34[0] + h2[0] * sw3[0] + h2[1] * sw3[1] + h2[2] * sw3[2];
        y[r] = h3 * sw4[0] + h3 * z0 * sw4[1] + sb34[1];

        k++;
        if (k == 1023u) {
            k = 0u; i++;
            Ai4  = *(const float4*)(g_AB + i * 16u);
            Ai4e = g_AB[i * 16u + 4u];
        }
    }
    *(float4*)(out + p0) = make_float4(y[0], y[1], y[2], y[3]);
}

// ---------------------------------------------------------------- launch
extern "C" void kernel_launch(void* const* d_in, const int* in_sizes, int n_in,
                              void* d_out, int out_size) {
    const float* x    = (const float*)d_in[0];
    const int*   ei   = (const int*)  d_in[1];
    const float* ew   = (const float*)d_in[2];
    const float* dist = (const float*)d_in[3];
    const float* lags = (const float*)d_in[4];
    const float* lz   = (const float*)d_in[5];
    const float* a2d  = (const float*)d_in[6];
    const float* a2o  = (const float*)d_in[7];
    const float* d2a  = (const float*)d_in[8];
    const float* o2a  = (const float*)d_in[9];
    const float* vr   = (const float*)d_in[10];
    const float* Wz   = (const float*)d_in[11];
    const float* bz   = (const float*)d_in[12];
    // d_in[13], d_in[14] = Wr, br — dead (H0 == 0 makes the reset gate a no-op)
    const float* Wh   = (const float*)d_in[15];
    const float* bh   = (const float*)d_in[16];
    const float* w1   = (const float*)d_in[17];
    const float* b1   = (const float*)d_in[18];
    const float* w2   = (const float*)d_in[19];
    const float* b2   = (const float*)d_in[20];
    const float* w3   = (const float*)d_in[21];
    const float* b3   = (const float*)d_in[22];
    const float* w4   = (const float*)d_in[23];
    const float* b4   = (const float*)d_in[24];
    float* out = (float*)d_out;

    k_zero<<<(NN * CI + 255) / 256, 256>>>();
    k_deg<<<(NE + 255) / 256, 256>>>(ei, ew);
    k_agg<<<(NE + 255) / 256, 256>>>(ei, x);
    k_node<<<NN / 8, 256>>>(x, Wz, bz, Wh, bh, w1);
    k_pairs<<<PP / (256 * 4), 256>>>(dist, lags, lz, a2d, a2o, d2a, o2a, vr,
                                     w1, b1, w2, b2, w3, b3, w4, b4, out);
}

// round 3
// speedup vs baseline: 1.3733x; 1.0643x over previous
#include <cuda_runtime.h>
#include <math.h>

#define NN   1024            // nodes
#define NE   (32 * NN)       // edges
#define CI   8               // in channels
#define NM1  1023
#define PP   (NN * NM1)      // pairs

// ---- scratch (device globals; zero-initialized at module load;
//      re-zeroed by k_pairs tail each launch so every call sees zeros) ----
__device__ float g_deg_out[NN];
__device__ float g_deg_in[NN];
__device__ float g_pfx[NN * CI];
__device__ float g_pbx[NN * CI];
// A at [n*16+0..4], B at [n*16+8..12]; fully rewritten each launch
__device__ float g_AB[NN * 16];

// vectorized global float4 reduction (sm_90+)
__device__ __forceinline__ void red4(float* p, float a, float b, float c, float d) {
    asm volatile("red.global.add.v4.f32 [%0], {%1,%2,%3,%4};"
                 :: "l"(p), "f"(a), "f"(b), "f"(c), "f"(d) : "memory");
}

// ---------------------------------------------------------------- degrees
__global__ void k_deg(const int* __restrict__ ei, const float* __restrict__ w) {
    int e = blockIdx.x * blockDim.x + threadIdx.x;
    if (e >= NE) return;
    int r = ei[e];
    int c = ei[NE + e];
    float we = w[e];
    atomicAdd(&g_deg_out[r], we);
    atomicAdd(&g_deg_in[c], we);
}

// ---------------------------------------------------------------- edge aggregation
// thread per EDGE: pf(x)[col] += x[row]/deg_out[row]; pb(x)[row] += x[col]/deg_in[row]
// (reference indexes deg_in by ROW — quirk kept)
__global__ void k_agg(const int* __restrict__ ei, const float* __restrict__ x) {
    int e = blockIdx.x * blockDim.x + threadIdx.x;
    if (e >= NE) return;
    int r = ei[e];
    int c = ei[NE + e];
    float inv_do = __fdividef(1.f, g_deg_out[r]);
    float inv_di = __fdividef(1.f, g_deg_in[r]);
    const float4* xr = (const float4*)(x + r * 8);
    const float4* xc = (const float4*)(x + c * 8);
    float4 a0 = xr[0], a1 = xr[1];
    float4 b0 = xc[0], b1 = xc[1];
    red4(&g_pfx[c * 8],     inv_do * a0.x, inv_do * a0.y, inv_do * a0.z, inv_do * a0.w);
    red4(&g_pfx[c * 8 + 4], inv_do * a1.x, inv_do * a1.y, inv_do * a1.z, inv_do * a1.w);
    red4(&g_pbx[r * 8],     inv_di * b0.x, inv_di * b0.y, inv_di * b0.z, inv_di * b0.w);
    red4(&g_pbx[r * 8 + 4], inv_di * b1.x, inv_di * b1.y, inv_di * b1.z, inv_di * b1.w);
}

// ---------------------------------------------------------------- per-node GRU + A/B
// 4 nodes / 128-thread block, grid=256. All weights staged in smem.
// Phase 1 (warp per node, lane = out channel c):
//   z = bz[c] + x·(W[0,0]+W[1,0]) + pfx·W[0,1] + pbx·W[1,1]  (x-rows 0:8 only; H0==0)
//   o = relu((1 - sigmoid(z)) * tanh(h))
// Phase 2 (lanes 0..9 of each warp): A/B = 40-long dots of [o, x] with w1 halves.
__global__ void __launch_bounds__(128)
k_node(const float* __restrict__ x,
       const float* __restrict__ Wz, const float* __restrict__ bz,
       const float* __restrict__ Wh, const float* __restrict__ bh,
       const float* __restrict__ w1) {
    __shared__ float swz0[8][32], swz1[8][32], swz2[8][32];
    __shared__ float swh0[8][32], swh1[8][32], swh2[8][32];
    __shared__ float sw1s[80][5];
    __shared__ float so[4][33];

    int t = threadIdx.x;
    // stage gate weights (combined x-weight = W[0,0]+W[1,0])
    for (int idx = t; idx < 256; idx += 128) {
        int k = idx >> 5, c = idx & 31, o = k * 32 + c;
        swz0[k][c] = __ldg(Wz + o) + __ldg(Wz + 2560 + o);
        swz1[k][c] = __ldg(Wz + 1280 + o);
        swz2[k][c] = __ldg(Wz + 3840 + o);
        swh0[k][c] = __ldg(Wh + o) + __ldg(Wh + 2560 + o);
        swh1[k][c] = __ldg(Wh + 1280 + o);
        swh2[k][c] = __ldg(Wh + 3840 + o);
    }
    for (int idx = t; idx < 400; idx += 128)
        sw1s[idx / 5][idx % 5] = __ldg(w1 + idx);
    __syncthreads();

    int wid = t >> 5, lane = t & 31;
    int n = blockIdx.x * 4 + wid;
    const int c = lane;

    float xv[8], pf[8], pb[8];
#pragma unroll
    for (int k = 0; k < 8; k++) {
        xv[k] = __ldg(x + n * 8 + k);
        pf[k] = g_pfx[n * 8 + k];
        pb[k] = g_pbx[n * 8 + k];
    }

    float z = __ldg(bz + c);
    float h = __ldg(bh + c);
#pragma unroll
    for (int k = 0; k < 8; k++) {
        z += xv[k] * swz0[k][c] + pf[k] * swz1[k][c] + pb[k] * swz2[k][c];
        h += xv[k] * swh0[k][c] + pf[k] * swh1[k][c] + pb[k] * swh2[k][c];
    }
    float sig = 1.f / (1.f + __expf(-z));
    float Hn  = (1.f - sig) * tanhf(h);
    so[wid][c] = fmaxf(Hn, 0.f);
    __syncwarp();

    if (lane < 10) {
        int half = lane / 5;           // 0 -> A (out[ii] rows 0..39), 1 -> B (rows 40..79)
        int m    = lane - half * 5;
        int base = half * 40;
        float acc = 0.f;
#pragma unroll
        for (int cc = 0; cc < 32; cc++)
            acc += so[wid][cc] * sw1s[base + cc][m];
#pragma unroll
        for (int k = 0; k < 8; k++)
            acc += xv[k] * sw1s[base + 32 + k][m];
        g_AB[n * 16 + half * 8 + m] = acc;
    }
}

// ---------------------------------------------------------------- pair MLP (the big one)
// 4 pairs per thread, float4 streaming loads/stores; small weights staged in smem.
// Also re-zeroes accumulator scratch for the next launch (replaces k_zero).
__global__ void __launch_bounds__(256)
k_pairs(const float* __restrict__ dist, const float* __restrict__ lags,
        const float* __restrict__ lz_,  const float* __restrict__ a2d,
        const float* __restrict__ a2o,  const float* __restrict__ d2a,
        const float* __restrict__ o2a,  const float* __restrict__ vr,
        const float* __restrict__ w1,   const float* __restrict__ b1,
        const float* __restrict__ w2,   const float* __restrict__ b2,
        const float* __restrict__ w3,   const float* __restrict__ b3,
        const float* __restrict__ w4,   const float* __restrict__ b4,
        float* __restrict__ out) {
    // tail-zero scratch (dead by this point in the launch): 18432 floats
    {
        int zi = blockIdx.x * blockDim.x + threadIdx.x;   // 0..261k
        if (zi < NN / 2) ((float2*)g_deg_out)[zi] = make_float2(0.f, 0.f);
        else if (zi < NN) ((float2*)g_deg_in)[zi - NN / 2] = make_float2(0.f, 0.f);
        else if (zi < NN + NN * CI / 4) {
            ((float4*)g_pfx)[zi - NN] = make_float4(0.f, 0.f, 0.f, 0.f);
        } else if (zi < NN + NN * CI / 2) {
            ((float4*)g_pbx)[zi - NN - NN * CI / 4] = make_float4(0.f, 0.f, 0.f, 0.f);
        }
    }

    __shared__ float sw1[45], sb1[5], sw2[15], sb2[3], sw3[3], sw4[2], sb34[2];
    int t = threadIdx.x;
    if (t < 45) sw1[t] = w1[400 + t];          // w1 rows 80..88 flat
    else if (t < 50) sb1[t - 45] = b1[t - 45];
    else if (t < 65) sw2[t - 50] = w2[t - 50];
    else if (t < 68) sb2[t - 65] = b2[t - 65];
    else if (t < 71) sw3[t - 68] = w3[t - 68];
    else if (t < 73) sw4[t - 71] = w4[t - 71];
    else if (t == 73) sb34[0] = b3[0];
    else if (t == 74) sb34[1] = b4[0];
    __syncthreads();

    int tid = blockIdx.x * blockDim.x + threadIdx.x;
    int p0  = tid * 4;
    if (p0 >= PP) return;

    float4 v_d  = *(const float4*)(dist + p0);
    float4 v_lg = *(const float4*)(lags + p0);
    float4 v_z0 = *(const float4*)(lz_  + p0);
    float4 v_td = *(const float4*)(a2d  + p0);
    float4 v_to = *(const float4*)(a2o  + p0);
    float4 v_da = *(const float4*)(d2a  + p0);
    float4 v_oa = *(const float4*)(o2a  + p0);
    float4 v_vv = *(const float4*)(vr   + p0);
    float dA[4]  = {v_d.x,  v_d.y,  v_d.z,  v_d.w};
    float lgA[4] = {v_lg.x, v_lg.y, v_lg.z, v_lg.w};
    float z0A[4] = {v_z0.x, v_z0.y, v_z0.z, v_z0.w};
    float tdA[4] = {v_td.x, v_td.y, v_td.z, v_td.w};
    float toA[4] = {v_to.x, v_to.y, v_to.z, v_to.w};
    float daA[4] = {v_da.x, v_da.y, v_da.z, v_da.w};
    float oaA[4] = {v_oa.x, v_oa.y, v_oa.z, v_oa.w};
    float vvA[4] = {v_vv.x, v_vv.y, v_vv.z, v_vv.w};

    unsigned i = (unsigned)p0 / 1023u;
    unsigned k = (unsigned)p0 - i * 1023u;

    float4 Ai4  = *(const float4*)(g_AB + i * 16u);
    float  Ai4e = g_AB[i * 16u + 4u];

    float y[4];
#pragma unroll
    for (int r = 0; r < 4; r++) {
        unsigned j = (k < i) ? k : (k + 1u);
        float4 Bj4  = *(const float4*)(g_AB + j * 16u + 8u);
        float  Bj4e = g_AB[j * 16u + 12u];
        float AiB[5] = {Ai4.x + Bj4.x, Ai4.y + Bj4.y, Ai4.z + Bj4.z,
                        Ai4.w + Bj4.w, Ai4e + Bj4e};
        float d = dA[r], lg = lgA[r], z0 = z0A[r];
        float td = tdA[r], to = toA[r], da = daA[r], oa = oaA[r], vv = vvA[r];

        float h1[5];
#pragma unroll
        for (int m = 0; m < 5; m++) {
            float v = AiB[m] + sb1[m];
            v += d  * (sw1[0 * 5 + m] + d * sw1[1 * 5 + m]);   // dist, dist^2
            v += lg * sw1[2 * 5 + m];
            v += z0 * sw1[3 * 5 + m];
            v += td * sw1[4 * 5 + m];
            v += to * sw1[5 * 5 + m];
            v += da * sw1[6 * 5 + m];
            v += oa * sw1[7 * 5 + m];
            v += vv * sw1[8 * 5 + m];
            h1[m] = fmaxf(v, 0.f);
        }
        float h2[3];
#pragma unroll
        for (int q = 0; q < 3; q++) {
            float v = sb2[q];
#pragma unroll
            for (int m = 0; m < 5; m++) v += h1[m] * sw2[m * 3 + q];
            h2[q] = fmaxf(v, 0.f);
        }
        float h3 = sb34[0] + h2[0] * sw3[0] + h2[1] * sw3[1] + h2[2] * sw3[2];
        y[r] = h3 * sw4[0] + h3 * z0 * sw4[1] + sb34[1];

        k++;
        if (k == 1023u) {
            k = 0u; i++;
            Ai4  = *(const float4*)(g_AB + i * 16u);
            Ai4e = g_AB[i * 16u + 4u];
        }
    }
    *(float4*)(out + p0) = make_float4(y[0], y[1], y[2], y[3]);
}

// ---------------------------------------------------------------- launch
extern "C" void kernel_launch(void* const* d_in, const int* in_sizes, int n_in,
                              void* d_out, int out_size) {
    const float* x    = (const float*)d_in[0];
    const int*   ei   = (const int*)  d_in[1];
    const float* ew   = (const float*)d_in[2];
    const float* dist = (const float*)d_in[3];
    const float* lags = (const float*)d_in[4];
    const float* lz   = (const float*)d_in[5];
    const float* a2d  = (const float*)d_in[6];
    const float* a2o  = (const float*)d_in[7];
    const float* d2a  = (const float*)d_in[8];
    const float* o2a  = (const float*)d_in[9];
    const float* vr   = (const float*)d_in[10];
    const float* Wz   = (const float*)d_in[11];
    const float* bz   = (const float*)d_in[12];
    // d_in[13], d_in[14] = Wr, br — dead (H0 == 0 makes the reset gate a no-op)
    const float* Wh   = (const float*)d_in[15];
    const float* bh   = (const float*)d_in[16];
    const float* w1   = (const float*)d_in[17];
    const float* b1   = (const float*)d_in[18];
    const float* w2   = (const float*)d_in[19];
    const float* b2   = (const float*)d_in[20];
    const float* w3   = (const float*)d_in[21];
    const float* b3   = (const float*)d_in[22];
    const float* w4   = (const float*)d_in[23];
    const float* b4   = (const float*)d_in[24];
    float* out = (float*)d_out;

    k_deg<<<(NE + 255) / 256, 256>>>(ei, ew);
    k_agg<<<(NE + 255) / 256, 256>>>(ei, x);
    k_node<<<NN / 4, 128>>>(x, Wz, bz, Wh, bh, w1);
    k_pairs<<<PP / (256 * 4), 256>>>(dist, lags, lz, a2d, a2o, d2a, o2a, vr,
                                     w1, b1, w2, b2, w3, b3, w4, b4, out);
}

// round 5
// speedup vs baseline: 1.5638x; 1.1387x over previous
#include <cuda_runtime.h>
#include <math.h>

#define NN   1024            // nodes
#define NE   (32 * NN)       // edges
#define CI   8               // in channels
#define NM1  1023
#define PP   (NN * NM1)      // pairs
#define PAIRS_PER_BLK 512
#define NBLK_PAIRS (PP / PAIRS_PER_BLK)   // 2046

// ---- scratch (device globals; zero-init at load; re-zeroed by k_pairs tail) ----
__device__ float g_deg_out[NN];
__device__ float g_deg_in[NN];
__device__ float g_pfx[NN * CI];
__device__ float g_pbx[NN * CI];
__device__ float g_A[NN * 5];   // per-node contribution to w1 via out[ii] slot
__device__ float g_B[NN * 5];   // per-node contribution to w1 via out[jj] slot

// vectorized global float4 reduction (sm_90+)
__device__ __forceinline__ void red4(float* p, float a, float b, float c, float d) {
    asm volatile("red.global.add.v4.f32 [%0], {%1,%2,%3,%4};"
                 :: "l"(p), "f"(a), "f"(b), "f"(c), "f"(d) : "memory");
}

// ---------------------------------------------------------------- degrees
__global__ void k_deg(const int* __restrict__ ei, const float* __restrict__ w) {
    int e = blockIdx.x * blockDim.x + threadIdx.x;
    if (e >= NE) return;
    int r = ei[e];
    int c = ei[NE + e];
    float we = w[e];
    atomicAdd(&g_deg_out[r], we);
    atomicAdd(&g_deg_in[c], we);
}

// ---------------------------------------------------------------- edge aggregation
// thread per EDGE: pf(x)[col] += x[row]/deg_out[row]; pb(x)[row] += x[col]/deg_in[row]
// (reference indexes deg_in by ROW — quirk kept)
__global__ void k_agg(const int* __restrict__ ei, const float* __restrict__ x) {
    int e = blockIdx.x * blockDim.x + threadIdx.x;
    if (e >= NE) return;
    int r = ei[e];
    int c = ei[NE + e];
    float inv_do = __fdividef(1.f, g_deg_out[r]);
    float inv_di = __fdividef(1.f, g_deg_in[r]);
    const float4* xr = (const float4*)(x + r * 8);
    const float4* xc = (const float4*)(x + c * 8);
    float4 a0 = xr[0], a1 = xr[1];
    float4 b0 = xc[0], b1 = xc[1];
    red4(&g_pfx[c * 8],     inv_do * a0.x, inv_do * a0.y, inv_do * a0.z, inv_do * a0.w);
    red4(&g_pfx[c * 8 + 4], inv_do * a1.x, inv_do * a1.y, inv_do * a1.z, inv_do * a1.w);
    red4(&g_pbx[r * 8],     inv_di * b0.x, inv_di * b0.y, inv_di * b0.z, inv_di * b0.w);
    red4(&g_pbx[r * 8 + 4], inv_di * b1.x, inv_di * b1.y, inv_di * b1.z, inv_di * b1.w);
}

// ---------------------------------------------------------------- per-node GRU + A/B
// 4 nodes / 128-thread block, grid=256. Weights staged in smem.
__global__ void __launch_bounds__(128)
k_node(const float* __restrict__ x,
       const float* __restrict__ Wz, const float* __restrict__ bz,
       const float* __restrict__ Wh, const float* __restrict__ bh,
       const float* __restrict__ w1) {
    __shared__ float swz0[8][32], swz1[8][32], swz2[8][32];
    __shared__ float swh0[8][32], swh1[8][32], swh2[8][32];
    __shared__ float sw1s[80][5];
    __shared__ float so[4][33];

    int t = threadIdx.x;
    for (int idx = t; idx < 256; idx += 128) {
        int k = idx >> 5, c = idx & 31, o = k * 32 + c;
        swz0[k][c] = __ldg(Wz + o) + __ldg(Wz + 2560 + o);
        swz1[k][c] = __ldg(Wz + 1280 + o);
        swz2[k][c] = __ldg(Wz + 3840 + o);
        swh0[k][c] = __ldg(Wh + o) + __ldg(Wh + 2560 + o);
        swh1[k][c] = __ldg(Wh + 1280 + o);
        swh2[k][c] = __ldg(Wh + 3840 + o);
    }
    for (int idx = t; idx < 400; idx += 128)
        sw1s[idx / 5][idx % 5] = __ldg(w1 + idx);
    __syncthreads();

    int wid = t >> 5, lane = t & 31;
    int n = blockIdx.x * 4 + wid;
    const int c = lane;

    float xv[8], pf[8], pb[8];
#pragma unroll
    for (int k = 0; k < 8; k++) {
        xv[k] = __ldg(x + n * 8 + k);
        pf[k] = g_pfx[n * 8 + k];
        pb[k] = g_pbx[n * 8 + k];
    }

    float z = __ldg(bz + c);
    float h = __ldg(bh + c);
#pragma unroll
    for (int k = 0; k < 8; k++) {
        z += xv[k] * swz0[k][c] + pf[k] * swz1[k][c] + pb[k] * swz2[k][c];
        h += xv[k] * swh0[k][c] + pf[k] * swh1[k][c] + pb[k] * swh2[k][c];
    }
    float sig = 1.f / (1.f + __expf(-z));
    float Hn  = (1.f - sig) * tanhf(h);
    so[wid][c] = fmaxf(Hn, 0.f);
    __syncwarp();

    if (lane < 10) {
        int half = lane / 5;           // 0 -> A (w1 rows 0..39), 1 -> B (rows 40..79)
        int m    = lane - half * 5;
        int base = half * 40;
        float acc = 0.f;
#pragma unroll
        for (int cc = 0; cc < 32; cc++)
            acc += so[wid][cc] * sw1s[base + cc][m];
#pragma unroll
        for (int k = 0; k < 8; k++)
            acc += xv[k] * sw1s[base + 32 + k][m];
        if (half == 0) g_A[n * 5 + m] = acc;
        else           g_B[n * 5 + m] = acc;
    }
}

// ---------------------------------------------------------------- pair MLP
// 256 threads x 2 pairs = 512 pairs/block. B rows for the block's j-window
// staged in smem (circular window of 514 rows from kb). Streams via float2.
__global__ void __launch_bounds__(256)
k_pairs(const float* __restrict__ dist, const float* __restrict__ lags,
        const float* __restrict__ lz_,  const float* __restrict__ a2d,
        const float* __restrict__ a2o,  const float* __restrict__ d2a,
        const float* __restrict__ o2a,  const float* __restrict__ vr,
        const float* __restrict__ w1,   const float* __restrict__ b1,
        const float* __restrict__ w2,   const float* __restrict__ b2,
        const float* __restrict__ w3,   const float* __restrict__ b3,
        const float* __restrict__ w4,   const float* __restrict__ b4,
        float* __restrict__ out) {
    __shared__ float sB[514 * 5];
    __shared__ float sA[2][5];
    __shared__ float sw1[45], sb1[5], sw2[15], sb2[3], sw3[3], sw4[2], sb34[2];

    const int pblk = blockIdx.x * PAIRS_PER_BLK;
    const int i0   = pblk / NM1;
    const int kb   = pblk - i0 * NM1;
    int t = threadIdx.x;

    // tail-zero scratch for next launch (dead by this point): 18432 floats
    {
        int zi = blockIdx.x * blockDim.x + t;
        if (zi < NN / 2) ((float2*)g_deg_out)[zi] = make_float2(0.f, 0.f);
        else if (zi < NN) ((float2*)g_deg_in)[zi - NN / 2] = make_float2(0.f, 0.f);
        else if (zi < NN + NN * CI / 4)
            ((float4*)g_pfx)[zi - NN] = make_float4(0.f, 0.f, 0.f, 0.f);
        else if (zi < NN + NN * CI / 2)
            ((float4*)g_pbx)[zi - NN - NN * CI / 4] = make_float4(0.f, 0.f, 0.f, 0.f);
    }

    // stage small weights
    if (t < 45) sw1[t] = w1[400 + t];          // w1 rows 80..88 flat
    else if (t < 50) sb1[t - 45] = b1[t - 45];
    else if (t < 65) sw2[t - 50] = w2[t - 50];
    else if (t < 68) sb2[t - 65] = b2[t - 65];
    else if (t < 71) sw3[t - 68] = w3[t - 68];
    else if (t < 73) sw4[t - 71] = w4[t - 71];
    else if (t == 73) sb34[0] = b3[0];
    else if (t == 74) sb34[1] = b4[0];
    else if (t >= 80 && t < 90) {              // stage A rows i0, i0+1
        int q = t - 80, ia = q / 5, m = q - ia * 5;
        int row = min(i0 + ia, NN - 1);
        sA[ia][m] = g_A[row * 5 + m];
    }
    // stage B circular window: row (kb + s) & 1023, s = 0..513
    for (int s = t; s < 514; s += 256) {
        int row = (kb + s) & (NN - 1);
#pragma unroll
        for (int m = 0; m < 5; m++) sB[s * 5 + m] = g_B[row * 5 + m];
    }
    __syncthreads();

    const int p0 = pblk + t * 2;

    float2 v_d  = *(const float2*)(dist + p0);
    float2 v_lg = *(const float2*)(lags + p0);
    float2 v_z0 = *(const float2*)(lz_  + p0);
    float2 v_td = *(const float2*)(a2d  + p0);
    float2 v_to = *(const float2*)(a2o  + p0);
    float2 v_da = *(const float2*)(d2a  + p0);
    float2 v_oa = *(const float2*)(o2a  + p0);
    float2 v_vv = *(const float2*)(vr   + p0);
    float dA[2]  = {v_d.x,  v_d.y};
    float lgA[2] = {v_lg.x, v_lg.y};
    float z0A[2] = {v_z0.x, v_z0.y};
    float tdA[2] = {v_td.x, v_td.y};
    float toA[2] = {v_to.x, v_to.y};
    float daA[2] = {v_da.x, v_da.y};
    float oaA[2] = {v_oa.x, v_oa.y};
    float vvA[2] = {v_vv.x, v_vv.y};

    // i, k for p0 (single wrap possible within a block)
    int k = kb + t * 2;
    int i = i0;
    if (k >= NM1) { k -= NM1; i = i0 + 1; }

    float y[2];
#pragma unroll
    for (int r = 0; r < 2; r++) {
        int j  = (k < i) ? k : (k + 1);
        int tw = (j - kb) & (NN - 1);          // circular window index, < 514
        const float* Bp = sB + tw * 5;
        const float* Ap = sA[i - i0];
        float d = dA[r], lg = lgA[r], z0 = z0A[r];
        float td = tdA[r], to = toA[r], da = daA[r], oa = oaA[r], vv = vvA[r];

        float h1[5];
#pragma unroll
        for (int m = 0; m < 5; m++) {
            float v = Ap[m] + Bp[m] + sb1[m];
            v += d  * (sw1[0 * 5 + m] + d * sw1[1 * 5 + m]);   // dist, dist^2
            v += lg * sw1[2 * 5 + m];
            v += z0 * sw1[3 * 5 + m];
            v += td * sw1[4 * 5 + m];
            v += to * sw1[5 * 5 + m];
            v += da * sw1[6 * 5 + m];
            v += oa * sw1[7 * 5 + m];
            v += vv * sw1[8 * 5 + m];
            h1[m] = fmaxf(v, 0.f);
        }
        float h2[3];
#pragma unroll
        for (int q = 0; q < 3; q++) {
            float v = sb2[q];
#pragma unroll
            for (int m = 0; m < 5; m++) v += h1[m] * sw2[m * 3 + q];
            h2[q] = fmaxf(v, 0.f);
        }
        float h3 = sb34[0] + h2[0] * sw3[0] + h2[1] * sw3[1] + h2[2] * sw3[2];
        y[r] = h3 * sw4[0] + h3 * z0 * sw4[1] + sb34[1];

        k++;
        if (k == NM1) { k = 0; i++; }
    }
    *(float2*)(out + p0) = make_float2(y[0], y[1]);
}

// ---------------------------------------------------------------- launch
extern "C" void kernel_launch(void* const* d_in, const int* in_sizes, int n_in,
                              void* d_out, int out_size) {
    const float* x    = (const float*)d_in[0];
    const int*   ei   = (const int*)  d_in[1];
    const float* ew   = (const float*)d_in[2];
    const float* dist = (const float*)d_in[3];
    const float* lags = (const float*)d_in[4];
    const float* lz   = (const float*)d_in[5];
    const float* a2d  = (const float*)d_in[6];
    const float* a2o  = (const float*)d_in[7];
    const float* d2a  = (const float*)d_in[8];
    const float* o2a  = (const float*)d_in[9];
    const float* vr   = (const float*)d_in[10];
    const float* Wz   = (const float*)d_in[11];
    const float* bz   = (const float*)d_in[12];
    // d_in[13], d_in[14] = Wr, br — dead (H0 == 0 makes the reset gate a no-op)
    const float* Wh   = (const float*)d_in[15];
    const float* bh   = (const float*)d_in[16];
    const float* w1   = (const float*)d_in[17];
    const float* b1   = (const float*)d_in[18];
    const float* w2   = (const float*)d_in[19];
    const float* b2   = (const float*)d_in[20];
    const float* w3   = (const float*)d_in[21];
    const float* b3   = (const float*)d_in[22];
    const float* w4   = (const float*)d_in[23];
    const float* b4   = (const float*)d_in[24];
    float* out = (float*)d_out;

    k_deg<<<(NE + 255) / 256, 256>>>(ei, ew);
    k_agg<<<(NE + 255) / 256, 256>>>(ei, x);
    k_node<<<NN / 4, 128>>>(x, Wz, bz, Wh, bh, w1);
    k_pairs<<<NBLK_PAIRS, 256>>>(dist, lags, lz, a2d, a2o, d2a, o2a, vr,
                                 w1, b1, w2, b2, w3, b3, w4, b4, out);
}